// round 8
// baseline (speedup 1.0000x reference)
#include <cuda_runtime.h>
#include <cuda_fp16.h>
#include <math.h>
#include <stdint.h>

// Problem constants
#define B_    2
#define T_    2048
#define C_    1024
#define H_    16
#define D_    64
#define M_    (B_ * T_)          // 4096
#define QKVN  (3 * H_ * D_)      // 3072

// Scratch (allocation-free rule: device globals) — fp16
__device__ __half g_xh [(size_t)M_ * C_];      // x in fp16
__device__ __half g_wqT[(size_t)QKVN * C_];    // w_qkv^T  [3072,1024]
__device__ __half g_wpT[(size_t)C_ * C_];      // w_proj^T [1024,1024]
__device__ __half g_qkv[(size_t)M_ * QKVN];
__device__ __half g_y  [(size_t)M_ * C_];

// ---------------------------------------------------------------------------
// helpers
// ---------------------------------------------------------------------------
__device__ __forceinline__ uint32_t pack2(float x, float y) {
    __half2 h = __floats2half2_rn(x, y);
    return *reinterpret_cast<uint32_t*>(&h);
}
__device__ __forceinline__ void mma_f16(float c[4], const uint32_t a[4],
                                        const uint32_t b[2]) {
    asm volatile(
        "mma.sync.aligned.m16n8k16.row.col.f32.f16.f16.f32 "
        "{%0,%1,%2,%3}, {%4,%5,%6,%7}, {%8,%9}, {%0,%1,%2,%3};\n"
        : "+f"(c[0]), "+f"(c[1]), "+f"(c[2]), "+f"(c[3])
        : "r"(a[0]), "r"(a[1]), "r"(a[2]), "r"(a[3]), "r"(b[0]), "r"(b[1]));
}
__device__ __forceinline__ void ldm_x4(uint32_t r[4], uint32_t addr) {
    asm volatile("ldmatrix.sync.aligned.m8n8.x4.shared.b16 {%0,%1,%2,%3}, [%4];"
        : "=r"(r[0]), "=r"(r[1]), "=r"(r[2]), "=r"(r[3]) : "r"(addr));
}
__device__ __forceinline__ void ldm_x4t(uint32_t r[4], uint32_t addr) {
    asm volatile("ldmatrix.sync.aligned.m8n8.x4.trans.shared.b16 {%0,%1,%2,%3}, [%4];"
        : "=r"(r[0]), "=r"(r[1]), "=r"(r[2]), "=r"(r[3]) : "r"(addr));
}
__device__ __forceinline__ void cpa16(uint32_t dst, const void* src) {
    asm volatile("cp.async.cg.shared.global [%0], [%1], 16;\n" :: "r"(dst), "l"(src));
}
#define CP_COMMIT() asm volatile("cp.async.commit_group;" ::: "memory")
#define CP_WAIT0()  asm volatile("cp.async.wait_group 0;"  ::: "memory")
#define CP_WAIT1()  asm volatile("cp.async.wait_group 1;"  ::: "memory")
#define CP_WAIT2()  asm volatile("cp.async.wait_group 2;"  ::: "memory")

// FMA-only exp2 (no MUFU); clamps below -120.
__device__ __forceinline__ float exp2_fast(float t) {
    t = fmaxf(t, -120.f);
    float r = rintf(t);
    float f = t - r;
    float p = fmaf(f, 0.009618129f, 0.055504109f);
    p = fmaf(f, p, 0.240226507f);
    p = fmaf(f, p, 0.693147181f);
    p = fmaf(f, p, 1.0f);
    return __int_as_float(__float_as_int(p) + (((int)r) << 23));
}

// ---------------------------------------------------------------------------
// pre-pass kernels
// ---------------------------------------------------------------------------
__global__ void convert_x(const float* __restrict__ x, __half* __restrict__ xh,
                          int n4) {
    int i = blockIdx.x * blockDim.x + threadIdx.x;
    if (i < n4) {
        float4 v = reinterpret_cast<const float4*>(x)[i];
        reinterpret_cast<uint2*>(xh)[i] = make_uint2(pack2(v.x, v.y), pack2(v.z, v.w));
    }
}
// wt[n][k] = (half) w[k][n];  w: [K,N] fp32 row-major
__global__ void transpose_w(const float* __restrict__ w, __half* __restrict__ wt,
                            int K, int N) {
    __shared__ __half t[32][33];
    const int n0 = blockIdx.x * 32, k0 = blockIdx.y * 32;
    const int tx = threadIdx.x, ty = threadIdx.y;
    #pragma unroll
    for (int j = 0; j < 32; j += 8)
        t[ty + j][tx] = __float2half(w[(size_t)(k0 + ty + j) * N + n0 + tx]);
    __syncthreads();
    #pragma unroll
    for (int j = 0; j < 32; j += 8)
        wt[(size_t)(n0 + ty + j) * K + k0 + tx] = t[tx][ty + j];
}

// ---------------------------------------------------------------------------
// gemm_cp: C[M,N] = A[M,K] @ Bt[N,K]^T, fp16 K-major operands.
// 128x128 tile, BK=32, 4-stage cp.async, 256 threads (8 warps 4x2),
// warp tile 32x64, ONE __syncthreads per k-chunk.  (round-7 known-good)
// ---------------------------------------------------------------------------
#define GSTAGE 20480                    // A tile 10240B + B tile 10240B
#define GEMM_SMEM (4 * GSTAGE)

template <typename TC>
__global__ __launch_bounds__(256, 2) void gemm_cp(
    const __half* __restrict__ A, const __half* __restrict__ Bt,
    TC* __restrict__ Cm, int M, int N, int K)
{
    extern __shared__ __align__(128) char smem[];
    uint32_t sb;
    asm("{ .reg .u64 t; cvta.to.shared.u64 t, %1; cvt.u32.u64 %0, t; }"
        : "=r"(sb) : "l"(smem));

    const int tid  = threadIdx.x;
    const int lane = tid & 31;
    const int warp = tid >> 5;
    const int wm = warp >> 1, wn = warp & 1;
    const int g = lane >> 2, t = lane & 3;
    const int m0 = blockIdx.y * 128;
    const int n0 = blockIdx.x * 128;
    const int nk = K >> 5;

    const __half* Abase = A + (size_t)m0 * K;
    const __half* Bbase = Bt + (size_t)n0 * K;

    const int r0c = tid >> 1, c0c = (tid & 1) * 2;

    auto load_chunk = [&](int c, int s) {
        const uint32_t base = sb + s * GSTAGE;
        const __half* Ac = Abase + (size_t)c * 32;
        const __half* Bc = Bbase + (size_t)c * 32;
        #pragma unroll
        for (int i = 0; i < 2; i++) {
            const uint32_t off = (uint32_t)r0c * 80 + (c0c + i) * 16;
            cpa16(base + off,         Ac + (size_t)r0c * K + (c0c + i) * 8);
            cpa16(base + 10240 + off, Bc + (size_t)r0c * K + (c0c + i) * 8);
        }
        CP_COMMIT();
    };

    uint32_t aAddr[2], bAddr[4];
    #pragma unroll
    for (int mt = 0; mt < 2; mt++)
        aAddr[mt] = sb + (wm * 32 + mt * 16 + (lane & 15)) * 80
                       + ((lane >> 4) * 8) * 2;
    #pragma unroll
    for (int ntp = 0; ntp < 4; ntp++)
        bAddr[ntp] = sb + 10240
                   + (wn * 64 + ntp * 16 + ((lane >> 4) & 1) * 8 + (lane & 7)) * 80
                   + (((lane >> 3) & 1) * 8) * 2;

    load_chunk(0, 0); load_chunk(1, 1); load_chunk(2, 2);

    float acc[2][8][4];
    #pragma unroll
    for (int mt = 0; mt < 2; mt++)
        #pragma unroll
        for (int nt = 0; nt < 8; nt++)
            #pragma unroll
            for (int j = 0; j < 4; j++) acc[mt][nt][j] = 0.f;

    for (int kt = 0; kt < nk; kt++) {
        const int s = kt & 3;
        if (kt < nk - 2)       CP_WAIT2();
        else if (kt == nk - 2) CP_WAIT1();
        else                   CP_WAIT0();
        __syncthreads();                       // single barrier per chunk
        if (kt + 3 < nk) load_chunk(kt + 3, (kt + 3) & 3);

        const uint32_t so = (uint32_t)s * GSTAGE;
        #pragma unroll
        for (int kk = 0; kk < 2; kk++) {
            const uint32_t ko = kk * 32;
            uint32_t af[2][4], bf[4][4];
            ldm_x4(af[0], aAddr[0] + so + ko);
            ldm_x4(af[1], aAddr[1] + so + ko);
            #pragma unroll
            for (int ntp = 0; ntp < 4; ntp++)
                ldm_x4(bf[ntp], bAddr[ntp] + so + ko);
            #pragma unroll
            for (int mt = 0; mt < 2; mt++)
                #pragma unroll
                for (int nt = 0; nt < 8; nt++)
                    mma_f16(acc[mt][nt], af[mt], &bf[nt >> 1][(nt & 1) * 2]);
        }
    }

    #pragma unroll
    for (int mt = 0; mt < 2; mt++) {
        const int r0 = m0 + wm * 32 + mt * 16 + g;
        #pragma unroll
        for (int nt = 0; nt < 8; nt++) {
            const int c0 = n0 + wn * 64 + nt * 8 + 2 * t;
            if (sizeof(TC) == 2) {
                *reinterpret_cast<__half2*>((__half*)Cm + (size_t)r0 * N + c0) =
                    __floats2half2_rn(acc[mt][nt][0], acc[mt][nt][1]);
                *reinterpret_cast<__half2*>((__half*)Cm + (size_t)(r0 + 8) * N + c0) =
                    __floats2half2_rn(acc[mt][nt][2], acc[mt][nt][3]);
            } else {
                *reinterpret_cast<float2*>((float*)Cm + (size_t)r0 * N + c0) =
                    make_float2(acc[mt][nt][0], acc[mt][nt][1]);
                *reinterpret_cast<float2*>((float*)Cm + (size_t)(r0 + 8) * N + c0) =
                    make_float2(acc[mt][nt][2], acc[mt][nt][3]);
            }
        }
    }
}

// ---------------------------------------------------------------------------
// attn_f16: tensor-core flash attention, ONLINE softmax (log2 domain,
// FMA-only exp2).  BQ=128 (8 warps share each KV tile -> half the KV
// global/L2 traffic of BQ=64), BKV=64, 3-stage cp.async ring.
// Grid (T/128, B*H), 256 threads; each warp owns 16 query rows.
// ---------------------------------------------------------------------------
#define KVSTR   72                      // halves per KV row (144B, odd x 16B)
#define KVROWS  64
#define KVTILE  (KVROWS * KVSTR)        // halves per K (or V) tile
#define KVSTAGE_B (2 * KVTILE * 2)      // bytes per stage (K + V) = 18432
#define ATTN_SMEM (3 * KVSTAGE_B)       // 55296

__global__ __launch_bounds__(256) void attn_f16(
    const __half* __restrict__ qkv, const float* __restrict__ sink,
    __half* __restrict__ y)
{
    extern __shared__ __align__(16) __half KV[];

    const int tid  = threadIdx.x;
    const int lane = tid & 31;
    const int warp = tid >> 5;                              // 0..7
    const int g = lane >> 2, t = lane & 3;
    const int qt = (int)gridDim.x - 1 - (int)blockIdx.x;    // longest first
    const int bh = blockIdx.y;
    const int b = bh >> 4, h = bh & 15;
    const int q0 = qt * 128;
    const size_t rowbase = (size_t)b * T_;

    const int rg0 = q0 + warp * 16 + g;
    const int rg1 = rg0 + 8;

    // Q fragments, scale = (1/8)*log2(e) folded in (log2-domain scores)
    uint32_t qa[4][4];
    {
        const __half2 sc = __floats2half2_rn(0.18033688f, 0.18033688f);
        const __half2* qp0 = reinterpret_cast<const __half2*>(
            &qkv[(rowbase + rg0) * QKVN + h * D_]);
        const __half2* qp8 = qp0 + (size_t)8 * QKVN / 2;
        #pragma unroll
        for (int ks = 0; ks < 4; ks++) {
            __half2 v0 = __hmul2(qp0[8 * ks + t], sc);
            __half2 v1 = __hmul2(qp8[8 * ks + t], sc);
            __half2 v2 = __hmul2(qp0[8 * ks + t + 4], sc);
            __half2 v3 = __hmul2(qp8[8 * ks + t + 4], sc);
            qa[ks][0] = *reinterpret_cast<uint32_t*>(&v0);
            qa[ks][1] = *reinterpret_cast<uint32_t*>(&v1);
            qa[ks][2] = *reinterpret_cast<uint32_t*>(&v2);
            qa[ks][3] = *reinterpret_cast<uint32_t*>(&v3);
        }
    }

    // ldmatrix base addresses (stage 0)
    uint32_t sbase;
    asm("{ .reg .u64 tt; cvta.to.shared.u64 tt, %1; cvt.u32.u64 %0, tt; }"
        : "=r"(sbase) : "l"(KV));
    uint32_t addrK[4], addrV[4];
    {
        const int kvK = ((lane >> 4) & 1) * 8 + (lane & 7);
        const int dK  = ((lane >> 3) & 1) * 8;
        #pragma unroll
        for (int kg = 0; kg < 4; kg++)
            addrK[kg] = sbase + ((kvK + 16 * kg) * KVSTR + dK) * 2;
        const uint32_t vbase = sbase + KVTILE * 2;
        const int kvV = ((lane >> 3) & 1) * 8 + (lane & 7);
        #pragma unroll
        for (int dtp = 0; dtp < 4; dtp++) {
            const int dV = dtp * 16 + ((lane >> 4) & 1) * 8;
            addrV[dtp] = vbase + (kvV * KVSTR + dV) * 2;
        }
    }

    // KV tile loader: 64 rows x (K+V) = 1024 16B-chunks, 4 per thread
    auto load_kv = [&](int j, int s) {
        const uint32_t base = sbase + (uint32_t)s * KVSTAGE_B;
        const int j0 = j * 64;
        #pragma unroll
        for (int i = 0; i < 4; i++) {
            const int id = tid + 256 * i;          // 0..1023
            const int kv = id >> 9;                // 0 = K, 1 = V
            const int r  = (id >> 3) & 63;
            const int c16 = id & 7;
            const size_t src = (rowbase + j0 + r) * QKVN
                             + (size_t)(1 + kv) * H_ * D_ + h * D_ + c16 * 8;
            cpa16(base + kv * (KVTILE * 2) + r * (KVSTR * 2) + c16 * 16,
                  &qkv[src]);
        }
        CP_COMMIT();
    };

    // online softmax state (log2 domain; sink: m = sink*log2e, l = 1)
    float m0v = sink[h] * 1.44269504f, m1v = m0v;
    float l0 = 1.f, l1 = 1.f;
    float oacc[8][4];
    #pragma unroll
    for (int dt = 0; dt < 8; dt++)
        #pragma unroll
        for (int j = 0; j < 4; j++) oacc[dt][j] = 0.f;

    const int ntile = 2 * qt + 2;
    load_kv(0, 0);
    load_kv(1, 1);

    for (int j = 0; j < ntile; j++) {
        const int s = j % 3;
        if (j < ntile - 1) CP_WAIT1(); else CP_WAIT0();
        __syncthreads();
        if (j + 2 < ntile) load_kv(j + 2, (j + 2) % 3);

        const uint32_t so = (uint32_t)s * KVSTAGE_B;

        // S (log2 domain) = (Q*scale*log2e) . K^T   [16 x 64 per warp]
        float sacc[8][4];
        #pragma unroll
        for (int nt = 0; nt < 8; nt++)
            #pragma unroll
            for (int jj = 0; jj < 4; jj++) sacc[nt][jj] = 0.f;
        #pragma unroll
        for (int ks = 0; ks < 4; ks++) {
            #pragma unroll
            for (int kg = 0; kg < 4; kg++) {
                uint32_t bk[4];
                ldm_x4(bk, addrK[kg] + so + ks * 32);
                mma_f16(sacc[2 * kg],     qa[ks], &bk[0]);
                mma_f16(sacc[2 * kg + 1], qa[ks], &bk[2]);
            }
        }

        // causal mask (tiles overlapping/after this CTA's query range)
        const int j0 = j * 64;
        if (j0 + 64 > q0 + warp * 16) {
            #pragma unroll
            for (int nt = 0; nt < 8; nt++) {
                const int cg = j0 + nt * 8 + 2 * t;
                if (cg     > rg0) sacc[nt][0] = -1e30f;
                if (cg + 1 > rg0) sacc[nt][1] = -1e30f;
                if (cg     > rg1) sacc[nt][2] = -1e30f;
                if (cg + 1 > rg1) sacc[nt][3] = -1e30f;
            }
        }

        // row maxima (in-thread + quad shfl)
        float rmax0 = -1e30f, rmax1 = -1e30f;
        #pragma unroll
        for (int nt = 0; nt < 8; nt++) {
            rmax0 = fmaxf(rmax0, fmaxf(sacc[nt][0], sacc[nt][1]));
            rmax1 = fmaxf(rmax1, fmaxf(sacc[nt][2], sacc[nt][3]));
        }
        rmax0 = fmaxf(rmax0, __shfl_xor_sync(0xffffffffu, rmax0, 1));
        rmax0 = fmaxf(rmax0, __shfl_xor_sync(0xffffffffu, rmax0, 2));
        rmax1 = fmaxf(rmax1, __shfl_xor_sync(0xffffffffu, rmax1, 1));
        rmax1 = fmaxf(rmax1, __shfl_xor_sync(0xffffffffu, rmax1, 2));

        const float mn0 = fmaxf(m0v, rmax0);
        const float mn1 = fmaxf(m1v, rmax1);
        const float corr0 = exp2_fast(m0v - mn0);
        const float corr1 = exp2_fast(m1v - mn1);
        m0v = mn0; m1v = mn1;

        // P = 2^(S - m) (FMA-only); pack directly into mma A-fragments
        uint32_t pa[4][4];
        float ps0 = 0.f, ps1 = 0.f;
        #pragma unroll
        for (int kg = 0; kg < 4; kg++) {
            #pragma unroll
            for (int nn = 0; nn < 2; nn++) {
                const int nt = kg * 2 + nn;
                const float p0 = exp2_fast(sacc[nt][0] - mn0);
                const float p1 = exp2_fast(sacc[nt][1] - mn0);
                const float p2 = exp2_fast(sacc[nt][2] - mn1);
                const float p3 = exp2_fast(sacc[nt][3] - mn1);
                ps0 += p0 + p1;
                ps1 += p2 + p3;
                pa[kg][nn * 2 + 0] = pack2(p0, p1);
                pa[kg][nn * 2 + 1] = pack2(p2, p3);
            }
        }
        ps0 += __shfl_xor_sync(0xffffffffu, ps0, 1);
        ps0 += __shfl_xor_sync(0xffffffffu, ps0, 2);
        ps1 += __shfl_xor_sync(0xffffffffu, ps1, 1);
        ps1 += __shfl_xor_sync(0xffffffffu, ps1, 2);
        l0 = l0 * corr0 + ps0;
        l1 = l1 * corr1 + ps1;

        // rescale output accumulators (once per 64 keys)
        #pragma unroll
        for (int dt = 0; dt < 8; dt++) {
            oacc[dt][0] *= corr0; oacc[dt][1] *= corr0;
            oacc[dt][2] *= corr1; oacc[dt][3] *= corr1;
        }

        // O += P . V
        #pragma unroll
        for (int kg = 0; kg < 4; kg++) {
            const uint32_t koff = so + kg * (16 * KVSTR * 2);
            uint32_t bv[4][4];
            #pragma unroll
            for (int dtp = 0; dtp < 4; dtp++)
                ldm_x4t(bv[dtp], addrV[dtp] + koff);
            #pragma unroll
            for (int dt = 0; dt < 8; dt++)
                mma_f16(oacc[dt], pa[kg], &bv[dt >> 1][(dt & 1) * 2]);
        }
    }

    // write y (fp16)
    const float inv0 = 1.f / l0, inv1 = 1.f / l1;
    __half2* yp0 = reinterpret_cast<__half2*>(&y[(rowbase + rg0) * C_ + h * D_]);
    __half2* yp1 = reinterpret_cast<__half2*>(&y[(rowbase + rg1) * C_ + h * D_]);
    #pragma unroll
    for (int dt = 0; dt < 8; dt++) {
        yp0[4 * dt + t] = __floats2half2_rn(oacc[dt][0] * inv0, oacc[dt][1] * inv0);
        yp1[4 * dt + t] = __floats2half2_rn(oacc[dt][2] * inv1, oacc[dt][3] * inv1);
    }
}

// ---------------------------------------------------------------------------
extern "C" void kernel_launch(void* const* d_in, const int* in_sizes, int n_in,
                              void* d_out, int out_size)
{
    const float* x      = (const float*)d_in[0];   // [2,2048,1024]
    const float* w_qkv  = (const float*)d_in[1];   // [1024,3072]
    const float* w_proj = (const float*)d_in[2];   // [1024,1024]
    const float* sink   = (const float*)d_in[3];   // [16]
    float* out = (float*)d_out;                    // [4096,1024]

    __half *xh, *wqT, *wpT, *qkv, *yb;
    cudaGetSymbolAddress((void**)&xh,  g_xh);
    cudaGetSymbolAddress((void**)&wqT, g_wqT);
    cudaGetSymbolAddress((void**)&wpT, g_wpT);
    cudaGetSymbolAddress((void**)&qkv, g_qkv);
    cudaGetSymbolAddress((void**)&yb,  g_y);

    cudaFuncSetAttribute(gemm_cp<__half>,
        cudaFuncAttributeMaxDynamicSharedMemorySize, GEMM_SMEM);
    cudaFuncSetAttribute(gemm_cp<float>,
        cudaFuncAttributeMaxDynamicSharedMemorySize, GEMM_SMEM);
    cudaFuncSetAttribute(attn_f16,
        cudaFuncAttributeMaxDynamicSharedMemorySize, ATTN_SMEM);

    convert_x<<<(M_ * C_ / 4 + 255) / 256, 256>>>(x, xh, M_ * C_ / 4);
    transpose_w<<<dim3(QKVN / 32, C_ / 32), dim3(32, 8)>>>(w_qkv, wqT, C_, QKVN);
    transpose_w<<<dim3(C_ / 32, C_ / 32), dim3(32, 8)>>>(w_proj, wpT, C_, C_);

    gemm_cp<__half><<<dim3(QKVN / 128, M_ / 128), 256, GEMM_SMEM>>>(
        xh, wqT, qkv, M_, QKVN, C_);
    attn_f16<<<dim3(T_ / 128, B_ * H_), 256, ATTN_SMEM>>>(qkv, sink, yb);
    gemm_cp<float><<<dim3(C_ / 128, M_ / 128), 256, GEMM_SMEM>>>(
        yb, wpT, out, M_, C_, C_);
}

// round 9
// speedup vs baseline: 1.2268x; 1.2268x over previous
#include <cuda_runtime.h>
#include <cuda_fp16.h>
#include <math.h>
#include <stdint.h>

// Problem constants
#define B_    2
#define T_    2048
#define C_    1024
#define H_    16
#define D_    64
#define M_    (B_ * T_)          // 4096
#define QKVN  (3 * H_ * D_)      // 3072

// Scratch (allocation-free rule: device globals) — fp16
__device__ __half g_xh [(size_t)M_ * C_];      // x in fp16
__device__ __half g_wqT[(size_t)QKVN * C_];    // w_qkv^T  [3072,1024]
__device__ __half g_wpT[(size_t)C_ * C_];      // w_proj^T [1024,1024]
__device__ __half g_qkv[(size_t)M_ * QKVN];
__device__ __half g_y  [(size_t)M_ * C_];

// ---------------------------------------------------------------------------
// helpers
// ---------------------------------------------------------------------------
__device__ __forceinline__ uint32_t pack2(float x, float y) {
    __half2 h = __floats2half2_rn(x, y);
    return *reinterpret_cast<uint32_t*>(&h);
}
__device__ __forceinline__ void mma_f16(float c[4], const uint32_t a[4],
                                        const uint32_t b[2]) {
    asm volatile(
        "mma.sync.aligned.m16n8k16.row.col.f32.f16.f16.f32 "
        "{%0,%1,%2,%3}, {%4,%5,%6,%7}, {%8,%9}, {%0,%1,%2,%3};\n"
        : "+f"(c[0]), "+f"(c[1]), "+f"(c[2]), "+f"(c[3])
        : "r"(a[0]), "r"(a[1]), "r"(a[2]), "r"(a[3]), "r"(b[0]), "r"(b[1]));
}
__device__ __forceinline__ void ldm_x4(uint32_t r[4], uint32_t addr) {
    asm volatile("ldmatrix.sync.aligned.m8n8.x4.shared.b16 {%0,%1,%2,%3}, [%4];"
        : "=r"(r[0]), "=r"(r[1]), "=r"(r[2]), "=r"(r[3]) : "r"(addr));
}
__device__ __forceinline__ void ldm_x4t(uint32_t r[4], uint32_t addr) {
    asm volatile("ldmatrix.sync.aligned.m8n8.x4.trans.shared.b16 {%0,%1,%2,%3}, [%4];"
        : "=r"(r[0]), "=r"(r[1]), "=r"(r[2]), "=r"(r[3]) : "r"(addr));
}
__device__ __forceinline__ void cpa16(uint32_t dst, const void* src) {
    asm volatile("cp.async.cg.shared.global [%0], [%1], 16;\n" :: "r"(dst), "l"(src));
}
#define CP_COMMIT() asm volatile("cp.async.commit_group;" ::: "memory")
#define CP_WAIT0()  asm volatile("cp.async.wait_group 0;"  ::: "memory")
#define CP_WAIT1()  asm volatile("cp.async.wait_group 1;"  ::: "memory")
#define CP_WAIT2()  asm volatile("cp.async.wait_group 2;"  ::: "memory")

// FMA-only exp2 (no MUFU); clamps below -120.
__device__ __forceinline__ float exp2_fast(float t) {
    t = fmaxf(t, -120.f);
    float r = rintf(t);
    float f = t - r;
    float p = fmaf(f, 0.009618129f, 0.055504109f);
    p = fmaf(f, p, 0.240226507f);
    p = fmaf(f, p, 0.693147181f);
    p = fmaf(f, p, 1.0f);
    return __int_as_float(__float_as_int(p) + (((int)r) << 23));
}

// ---------------------------------------------------------------------------
// pre-pass kernels
// ---------------------------------------------------------------------------
__global__ void convert_x(const float* __restrict__ x, __half* __restrict__ xh,
                          int n4) {
    int i = blockIdx.x * blockDim.x + threadIdx.x;
    if (i < n4) {
        float4 v = reinterpret_cast<const float4*>(x)[i];
        reinterpret_cast<uint2*>(xh)[i] = make_uint2(pack2(v.x, v.y), pack2(v.z, v.w));
    }
}
// wt[n][k] = (half) w[k][n];  w: [K,N] fp32 row-major
__global__ void transpose_w(const float* __restrict__ w, __half* __restrict__ wt,
                            int K, int N) {
    __shared__ __half t[32][33];
    const int n0 = blockIdx.x * 32, k0 = blockIdx.y * 32;
    const int tx = threadIdx.x, ty = threadIdx.y;
    #pragma unroll
    for (int j = 0; j < 32; j += 8)
        t[ty + j][tx] = __float2half(w[(size_t)(k0 + ty + j) * N + n0 + tx]);
    __syncthreads();
    #pragma unroll
    for (int j = 0; j < 32; j += 8)
        wt[(size_t)(n0 + ty + j) * K + k0 + tx] = t[tx][ty + j];
}

// ---------------------------------------------------------------------------
// gemm_cp: C[M,N] = A[M,K] @ Bt[N,K]^T, fp16 K-major operands.
// 128x128 CTA tile, BK=32, 4-stage cp.async, 128 threads = 4 warps (2x2),
// WARP TILE 64x64 (halves fragment traffic per HMMA vs 32x64 -> crossbar
// ceiling rises from ~39% to ~59% of tensor peak).
// Smem rows stride 40 halves (80B, odd multiple of 16B -> conflict-free).
// ---------------------------------------------------------------------------
#define GSTAGE 20480                    // A tile 10240B + B tile 10240B
#define GEMM_SMEM (4 * GSTAGE)

template <typename TC>
__global__ __launch_bounds__(128, 2) void gemm_cp(
    const __half* __restrict__ A, const __half* __restrict__ Bt,
    TC* __restrict__ Cm, int M, int N, int K)
{
    extern __shared__ __align__(128) char smem[];
    uint32_t sb;
    asm("{ .reg .u64 t; cvta.to.shared.u64 t, %1; cvt.u32.u64 %0, t; }"
        : "=r"(sb) : "l"(smem));

    const int tid  = threadIdx.x;
    const int lane = tid & 31;
    const int warp = tid >> 5;           // 0..3
    const int wm = warp >> 1, wn = warp & 1;
    const int g = lane >> 2, t = lane & 3;
    const int m0 = blockIdx.y * 128;
    const int n0 = blockIdx.x * 128;
    const int nk = K >> 5;

    const __half* Abase = A + (size_t)m0 * K;
    const __half* Bbase = Bt + (size_t)n0 * K;

    // cp.async: 1024 16B-chunks per stage (A 512 + B 512), 8 per thread
    auto load_chunk = [&](int c, int s) {
        const uint32_t base = sb + s * GSTAGE;
        const __half* Ac = Abase + (size_t)c * 32;
        const __half* Bc = Bbase + (size_t)c * 32;
        #pragma unroll
        for (int i = 0; i < 8; i++) {
            const int id  = tid + 128 * i;        // 0..1023
            const int ab  = id >> 9;              // 0 = A, 1 = B
            const int r   = (id >> 2) & 127;
            const int c16 = id & 3;
            const uint32_t off = ab * 10240u + (uint32_t)r * 80 + c16 * 16;
            const __half* src = (ab ? Bc : Ac) + (size_t)r * K + c16 * 8;
            cpa16(base + off, src);
        }
        CP_COMMIT();
    };

    // ldmatrix fragment addresses (stage 0)
    uint32_t aAddr[4], bAddr[4];
    #pragma unroll
    for (int mt = 0; mt < 4; mt++)
        aAddr[mt] = sb + (wm * 64 + mt * 16 + (lane & 15)) * 80
                       + ((lane >> 4) * 8) * 2;
    #pragma unroll
    for (int ntp = 0; ntp < 4; ntp++)
        bAddr[ntp] = sb + 10240
                   + (wn * 64 + ntp * 16 + ((lane >> 4) & 1) * 8 + (lane & 7)) * 80
                   + (((lane >> 3) & 1) * 8) * 2;

    load_chunk(0, 0); load_chunk(1, 1); load_chunk(2, 2);

    float acc[4][8][4];
    #pragma unroll
    for (int mt = 0; mt < 4; mt++)
        #pragma unroll
        for (int nt = 0; nt < 8; nt++)
            #pragma unroll
            for (int j = 0; j < 4; j++) acc[mt][nt][j] = 0.f;

    for (int kt = 0; kt < nk; kt++) {
        const int s = kt & 3;
        if (kt < nk - 2)       CP_WAIT2();
        else if (kt == nk - 2) CP_WAIT1();
        else                   CP_WAIT0();
        __syncthreads();                       // single barrier per chunk
        if (kt + 3 < nk) load_chunk(kt + 3, (kt + 3) & 3);

        const uint32_t so = (uint32_t)s * GSTAGE;
        #pragma unroll
        for (int kk = 0; kk < 2; kk++) {
            const uint32_t ko = kk * 32;       // 16 halves = 32B
            uint32_t af[4][4], bf[4][4];
            #pragma unroll
            for (int mt = 0; mt < 4; mt++)
                ldm_x4(af[mt], aAddr[mt] + so + ko);
            #pragma unroll
            for (int ntp = 0; ntp < 4; ntp++)
                ldm_x4(bf[ntp], bAddr[ntp] + so + ko);
            #pragma unroll
            for (int mt = 0; mt < 4; mt++)
                #pragma unroll
                for (int nt = 0; nt < 8; nt++)
                    mma_f16(acc[mt][nt], af[mt], &bf[nt >> 1][(nt & 1) * 2]);
        }
    }

    #pragma unroll
    for (int mt = 0; mt < 4; mt++) {
        const int r0 = m0 + wm * 64 + mt * 16 + g;
        #pragma unroll
        for (int nt = 0; nt < 8; nt++) {
            const int c0 = n0 + wn * 64 + nt * 8 + 2 * t;
            if (sizeof(TC) == 2) {
                *reinterpret_cast<__half2*>((__half*)Cm + (size_t)r0 * N + c0) =
                    __floats2half2_rn(acc[mt][nt][0], acc[mt][nt][1]);
                *reinterpret_cast<__half2*>((__half*)Cm + (size_t)(r0 + 8) * N + c0) =
                    __floats2half2_rn(acc[mt][nt][2], acc[mt][nt][3]);
            } else {
                *reinterpret_cast<float2*>((float*)Cm + (size_t)r0 * N + c0) =
                    make_float2(acc[mt][nt][0], acc[mt][nt][1]);
                *reinterpret_cast<float2*>((float*)Cm + (size_t)(r0 + 8) * N + c0) =
                    make_float2(acc[mt][nt][2], acc[mt][nt][3]);
            }
        }
    }
}

// ---------------------------------------------------------------------------
// attn_f16: round-7 config (best known): BQ=64, BKV=64, 128 threads = 4
// warps, online softmax (log2 domain, FMA-only exp2), 3-stage cp.async ring.
// ---------------------------------------------------------------------------
#define KVSTR   72                      // halves per KV row (144B, odd x 16B)
#define KVROWS  64
#define KVTILE  (KVROWS * KVSTR)        // halves per K (or V) tile
#define KVSTAGE_B (2 * KVTILE * 2)      // bytes per stage (K + V) = 18432
#define ATTN_SMEM (3 * KVSTAGE_B)       // 55296

__global__ __launch_bounds__(128) void attn_f16(
    const __half* __restrict__ qkv, const float* __restrict__ sink,
    __half* __restrict__ y)
{
    extern __shared__ __align__(16) __half KV[];

    const int tid  = threadIdx.x;
    const int lane = tid & 31;
    const int warp = tid >> 5;
    const int g = lane >> 2, t = lane & 3;
    const int qt = (int)gridDim.x - 1 - (int)blockIdx.x;   // longest first
    const int bh = blockIdx.y;
    const int b = bh >> 4, h = bh & 15;
    const int q0 = qt * 64;
    const size_t rowbase = (size_t)b * T_;

    const int rg0 = q0 + warp * 16 + g;
    const int rg1 = rg0 + 8;

    // Q fragments, scale = (1/8)*log2(e) folded in (log2-domain scores)
    uint32_t qa[4][4];
    {
        const __half2 sc = __floats2half2_rn(0.18033688f, 0.18033688f);
        const __half2* qp0 = reinterpret_cast<const __half2*>(
            &qkv[(rowbase + rg0) * QKVN + h * D_]);
        const __half2* qp8 = qp0 + (size_t)8 * QKVN / 2;
        #pragma unroll
        for (int ks = 0; ks < 4; ks++) {
            __half2 v0 = __hmul2(qp0[8 * ks + t], sc);
            __half2 v1 = __hmul2(qp8[8 * ks + t], sc);
            __half2 v2 = __hmul2(qp0[8 * ks + t + 4], sc);
            __half2 v3 = __hmul2(qp8[8 * ks + t + 4], sc);
            qa[ks][0] = *reinterpret_cast<uint32_t*>(&v0);
            qa[ks][1] = *reinterpret_cast<uint32_t*>(&v1);
            qa[ks][2] = *reinterpret_cast<uint32_t*>(&v2);
            qa[ks][3] = *reinterpret_cast<uint32_t*>(&v3);
        }
    }

    // ldmatrix base addresses (stage 0)
    uint32_t sbase;
    asm("{ .reg .u64 tt; cvta.to.shared.u64 tt, %1; cvt.u32.u64 %0, tt; }"
        : "=r"(sbase) : "l"(KV));
    uint32_t addrK[4], addrV[4];
    {
        const int kvK = ((lane >> 4) & 1) * 8 + (lane & 7);
        const int dK  = ((lane >> 3) & 1) * 8;
        #pragma unroll
        for (int kg = 0; kg < 4; kg++)
            addrK[kg] = sbase + ((kvK + 16 * kg) * KVSTR + dK) * 2;
        const uint32_t vbase = sbase + KVTILE * 2;
        const int kvV = ((lane >> 3) & 1) * 8 + (lane & 7);
        #pragma unroll
        for (int dtp = 0; dtp < 4; dtp++) {
            const int dV = dtp * 16 + ((lane >> 4) & 1) * 8;
            addrV[dtp] = vbase + (kvV * KVSTR + dV) * 2;
        }
    }

    // KV tile loader: 64 rows x (K+V) = 16KB per stage, 8 x 16B per thread
    auto load_kv = [&](int j, int s) {
        const uint32_t base = sbase + (uint32_t)s * KVSTAGE_B;
        const int j0 = j * 64;
        #pragma unroll
        for (int i = 0; i < 8; i++) {
            const int id = tid + 128 * i;          // 0..1023
            const int kv = id >> 9;                // 0 = K, 1 = V
            const int r  = (id >> 3) & 63;
            const int c16 = id & 7;
            const size_t src = (rowbase + j0 + r) * QKVN
                             + (size_t)(1 + kv) * H_ * D_ + h * D_ + c16 * 8;
            cpa16(base + kv * (KVTILE * 2) + r * (KVSTR * 2) + c16 * 16,
                  &qkv[src]);
        }
        CP_COMMIT();
    };

    // online softmax state (log2 domain; sink: m = sink*log2e, l = 1)
    float m0v = sink[h] * 1.44269504f, m1v = m0v;
    float l0 = 1.f, l1 = 1.f;
    float oacc[8][4];
    #pragma unroll
    for (int dt = 0; dt < 8; dt++)
        #pragma unroll
        for (int j = 0; j < 4; j++) oacc[dt][j] = 0.f;

    const int ntile = qt + 1;
    load_kv(0, 0);
    if (ntile > 1) load_kv(1, 1);

    for (int j = 0; j < ntile; j++) {
        const int s = j % 3;
        if (j < ntile - 1) CP_WAIT1(); else CP_WAIT0();
        __syncthreads();
        if (j + 2 < ntile) load_kv(j + 2, (j + 2) % 3);

        const uint32_t so = (uint32_t)s * KVSTAGE_B;

        // S (log2 domain) = (Q*scale*log2e) . K^T   [16 x 64 per warp]
        float sacc[8][4];
        #pragma unroll
        for (int nt = 0; nt < 8; nt++)
            #pragma unroll
            for (int jj = 0; jj < 4; jj++) sacc[nt][jj] = 0.f;
        #pragma unroll
        for (int ks = 0; ks < 4; ks++) {
            #pragma unroll
            for (int kg = 0; kg < 4; kg++) {
                uint32_t bk[4];
                ldm_x4(bk, addrK[kg] + so + ks * 32);
                mma_f16(sacc[2 * kg],     qa[ks], &bk[0]);
                mma_f16(sacc[2 * kg + 1], qa[ks], &bk[2]);
            }
        }

        // causal mask (diagonal tile only)
        const int j0 = j * 64;
        if (j0 >= q0) {
            #pragma unroll
            for (int nt = 0; nt < 8; nt++) {
                const int cg = j0 + nt * 8 + 2 * t;
                if (cg     > rg0) sacc[nt][0] = -1e30f;
                if (cg + 1 > rg0) sacc[nt][1] = -1e30f;
                if (cg     > rg1) sacc[nt][2] = -1e30f;
                if (cg + 1 > rg1) sacc[nt][3] = -1e30f;
            }
        }

        // row maxima (in-thread + quad shfl)
        float rmax0 = -1e30f, rmax1 = -1e30f;
        #pragma unroll
        for (int nt = 0; nt < 8; nt++) {
            rmax0 = fmaxf(rmax0, fmaxf(sacc[nt][0], sacc[nt][1]));
            rmax1 = fmaxf(rmax1, fmaxf(sacc[nt][2], sacc[nt][3]));
        }
        rmax0 = fmaxf(rmax0, __shfl_xor_sync(0xffffffffu, rmax0, 1));
        rmax0 = fmaxf(rmax0, __shfl_xor_sync(0xffffffffu, rmax0, 2));
        rmax1 = fmaxf(rmax1, __shfl_xor_sync(0xffffffffu, rmax1, 1));
        rmax1 = fmaxf(rmax1, __shfl_xor_sync(0xffffffffu, rmax1, 2));

        const float mn0 = fmaxf(m0v, rmax0);
        const float mn1 = fmaxf(m1v, rmax1);
        const float corr0 = exp2_fast(m0v - mn0);
        const float corr1 = exp2_fast(m1v - mn1);
        m0v = mn0; m1v = mn1;

        // P = 2^(S - m) (FMA-only); pack directly into mma A-fragments
        uint32_t pa[4][4];
        float ps0 = 0.f, ps1 = 0.f;
        #pragma unroll
        for (int kg = 0; kg < 4; kg++) {
            #pragma unroll
            for (int nn = 0; nn < 2; nn++) {
                const int nt = kg * 2 + nn;
                const float p0 = exp2_fast(sacc[nt][0] - mn0);
                const float p1 = exp2_fast(sacc[nt][1] - mn0);
                const float p2 = exp2_fast(sacc[nt][2] - mn1);
                const float p3 = exp2_fast(sacc[nt][3] - mn1);
                ps0 += p0 + p1;
                ps1 += p2 + p3;
                pa[kg][nn * 2 + 0] = pack2(p0, p1);
                pa[kg][nn * 2 + 1] = pack2(p2, p3);
            }
        }
        ps0 += __shfl_xor_sync(0xffffffffu, ps0, 1);
        ps0 += __shfl_xor_sync(0xffffffffu, ps0, 2);
        ps1 += __shfl_xor_sync(0xffffffffu, ps1, 1);
        ps1 += __shfl_xor_sync(0xffffffffu, ps1, 2);
        l0 = l0 * corr0 + ps0;
        l1 = l1 * corr1 + ps1;

        // rescale output accumulators (once per 64 keys)
        #pragma unroll
        for (int dt = 0; dt < 8; dt++) {
            oacc[dt][0] *= corr0; oacc[dt][1] *= corr0;
            oacc[dt][2] *= corr1; oacc[dt][3] *= corr1;
        }

        // O += P . V
        #pragma unroll
        for (int kg = 0; kg < 4; kg++) {
            const uint32_t koff = so + kg * (16 * KVSTR * 2);
            uint32_t bv[4][4];
            #pragma unroll
            for (int dtp = 0; dtp < 4; dtp++)
                ldm_x4t(bv[dtp], addrV[dtp] + koff);
            #pragma unroll
            for (int dt = 0; dt < 8; dt++)
                mma_f16(oacc[dt], pa[kg], &bv[dt >> 1][(dt & 1) * 2]);
        }
    }

    // write y (fp16)
    const float inv0 = 1.f / l0, inv1 = 1.f / l1;
    __half2* yp0 = reinterpret_cast<__half2*>(&y[(rowbase + rg0) * C_ + h * D_]);
    __half2* yp1 = reinterpret_cast<__half2*>(&y[(rowbase + rg1) * C_ + h * D_]);
    #pragma unroll
    for (int dt = 0; dt < 8; dt++) {
        yp0[4 * dt + t] = __floats2half2_rn(oacc[dt][0] * inv0, oacc[dt][1] * inv0);
        yp1[4 * dt + t] = __floats2half2_rn(oacc[dt][2] * inv1, oacc[dt][3] * inv1);
    }
}

// ---------------------------------------------------------------------------
extern "C" void kernel_launch(void* const* d_in, const int* in_sizes, int n_in,
                              void* d_out, int out_size)
{
    const float* x      = (const float*)d_in[0];   // [2,2048,1024]
    const float* w_qkv  = (const float*)d_in[1];   // [1024,3072]
    const float* w_proj = (const float*)d_in[2];   // [1024,1024]
    const float* sink   = (const float*)d_in[3];   // [16]
    float* out = (float*)d_out;                    // [4096,1024]

    __half *xh, *wqT, *wpT, *qkv, *yb;
    cudaGetSymbolAddress((void**)&xh,  g_xh);
    cudaGetSymbolAddress((void**)&wqT, g_wqT);
    cudaGetSymbolAddress((void**)&wpT, g_wpT);
    cudaGetSymbolAddress((void**)&qkv, g_qkv);
    cudaGetSymbolAddress((void**)&yb,  g_y);

    cudaFuncSetAttribute(gemm_cp<__half>,
        cudaFuncAttributeMaxDynamicSharedMemorySize, GEMM_SMEM);
    cudaFuncSetAttribute(gemm_cp<float>,
        cudaFuncAttributeMaxDynamicSharedMemorySize, GEMM_SMEM);
    cudaFuncSetAttribute(attn_f16,
        cudaFuncAttributeMaxDynamicSharedMemorySize, ATTN_SMEM);

    convert_x<<<(M_ * C_ / 4 + 255) / 256, 256>>>(x, xh, M_ * C_ / 4);
    transpose_w<<<dim3(QKVN / 32, C_ / 32), dim3(32, 8)>>>(w_qkv, wqT, C_, QKVN);
    transpose_w<<<dim3(C_ / 32, C_ / 32), dim3(32, 8)>>>(w_proj, wpT, C_, C_);

    gemm_cp<__half><<<dim3(QKVN / 128, M_ / 128), 128, GEMM_SMEM>>>(
        xh, wqT, qkv, M_, QKVN, C_);
    attn_f16<<<dim3(T_ / 64, B_ * H_), 128, ATTN_SMEM>>>(qkv, sink, yb);
    gemm_cp<float><<<dim3(C_ / 128, M_ / 128), 128, GEMM_SMEM>>>(
        yb, wpT, out, M_, C_, C_);
}

// round 10
// speedup vs baseline: 1.2649x; 1.0311x over previous
#include <cuda_runtime.h>
#include <cuda_fp16.h>
#include <math.h>
#include <stdint.h>

// Problem constants
#define B_    2
#define T_    2048
#define C_    1024
#define H_    16
#define D_    64
#define M_    (B_ * T_)          // 4096
#define QKVN  (3 * H_ * D_)      // 3072

// Scratch (allocation-free rule: device globals) — fp16
__device__ __half g_xh [(size_t)M_ * C_];      // x in fp16
__device__ __half g_wqT[(size_t)QKVN * C_];    // w_qkv^T  [3072,1024]
__device__ __half g_wpT[(size_t)C_ * C_];      // w_proj^T [1024,1024]
__device__ __half g_qkv[(size_t)M_ * QKVN];
__device__ __half g_y  [(size_t)M_ * C_];

// ---------------------------------------------------------------------------
// helpers
// ---------------------------------------------------------------------------
__device__ __forceinline__ uint32_t pack2(float x, float y) {
    __half2 h = __floats2half2_rn(x, y);
    return *reinterpret_cast<uint32_t*>(&h);
}
__device__ __forceinline__ void mma_f16(float c[4], const uint32_t a[4],
                                        const uint32_t b[2]) {
    asm volatile(
        "mma.sync.aligned.m16n8k16.row.col.f32.f16.f16.f32 "
        "{%0,%1,%2,%3}, {%4,%5,%6,%7}, {%8,%9}, {%0,%1,%2,%3};\n"
        : "+f"(c[0]), "+f"(c[1]), "+f"(c[2]), "+f"(c[3])
        : "r"(a[0]), "r"(a[1]), "r"(a[2]), "r"(a[3]), "r"(b[0]), "r"(b[1]));
}
__device__ __forceinline__ void ldm_x4(uint32_t r[4], uint32_t addr) {
    asm volatile("ldmatrix.sync.aligned.m8n8.x4.shared.b16 {%0,%1,%2,%3}, [%4];"
        : "=r"(r[0]), "=r"(r[1]), "=r"(r[2]), "=r"(r[3]) : "r"(addr));
}
__device__ __forceinline__ void ldm_x4t(uint32_t r[4], uint32_t addr) {
    asm volatile("ldmatrix.sync.aligned.m8n8.x4.trans.shared.b16 {%0,%1,%2,%3}, [%4];"
        : "=r"(r[0]), "=r"(r[1]), "=r"(r[2]), "=r"(r[3]) : "r"(addr));
}
__device__ __forceinline__ void cpa16(uint32_t dst, const void* src) {
    asm volatile("cp.async.cg.shared.global [%0], [%1], 16;\n" :: "r"(dst), "l"(src));
}
#define CP_COMMIT() asm volatile("cp.async.commit_group;" ::: "memory")
#define CP_WAIT0()  asm volatile("cp.async.wait_group 0;"  ::: "memory")
#define CP_WAIT1()  asm volatile("cp.async.wait_group 1;"  ::: "memory")
#define CP_WAIT2()  asm volatile("cp.async.wait_group 2;"  ::: "memory")

// FMA-only exp2 (no MUFU, no F2I): magic-constant round, degree-4 poly.
// Valid for t in [-120, 2^21]; clamps below.
__device__ __forceinline__ float exp2_fast(float t) {
    t = fmaxf(t, -120.f);
    const float MAGIC = 12582912.f;            // 1.5 * 2^23
    float fr = t + MAGIC;                      // round-to-nearest in mantissa
    float r  = fr - MAGIC;
    float f  = t - r;                          // f in [-0.5, 0.5]
    int ri   = __float_as_int(fr) - 0x4B400000;
    float p = fmaf(f, 0.009618129f, 0.055504109f);
    p = fmaf(f, p, 0.240226507f);
    p = fmaf(f, p, 0.693147181f);
    p = fmaf(f, p, 1.0f);
    return __int_as_float(__float_as_int(p) + (ri << 23));
}

// ---------------------------------------------------------------------------
// pre-pass kernels
// ---------------------------------------------------------------------------
__global__ void convert_x(const float* __restrict__ x, __half* __restrict__ xh,
                          int n4) {
    int i = blockIdx.x * blockDim.x + threadIdx.x;
    if (i < n4) {
        float4 v = reinterpret_cast<const float4*>(x)[i];
        reinterpret_cast<uint2*>(xh)[i] = make_uint2(pack2(v.x, v.y), pack2(v.z, v.w));
    }
}
// wt[n][k] = (half) w[k][n];  w: [K,N] fp32 row-major
__global__ void transpose_w(const float* __restrict__ w, __half* __restrict__ wt,
                            int K, int N) {
    __shared__ __half t[32][33];
    const int n0 = blockIdx.x * 32, k0 = blockIdx.y * 32;
    const int tx = threadIdx.x, ty = threadIdx.y;
    #pragma unroll
    for (int j = 0; j < 32; j += 8)
        t[ty + j][tx] = __float2half(w[(size_t)(k0 + ty + j) * N + n0 + tx]);
    __syncthreads();
    #pragma unroll
    for (int j = 0; j < 32; j += 8)
        wt[(size_t)(n0 + ty + j) * K + k0 + tx] = t[tx][ty + j];
}

// ---------------------------------------------------------------------------
// gemm_cp: round-9 known-good.  C[M,N] = A[M,K] @ Bt[N,K]^T, fp16 K-major.
// 128x128 CTA tile, BK=32, 4-stage cp.async, 128 threads = 4 warps (2x2),
// warp tile 64x64.
// ---------------------------------------------------------------------------
#define GSTAGE 20480                    // A tile 10240B + B tile 10240B
#define GEMM_SMEM (4 * GSTAGE)

template <typename TC>
__global__ __launch_bounds__(128, 2) void gemm_cp(
    const __half* __restrict__ A, const __half* __restrict__ Bt,
    TC* __restrict__ Cm, int M, int N, int K)
{
    extern __shared__ __align__(128) char smem[];
    uint32_t sb;
    asm("{ .reg .u64 t; cvta.to.shared.u64 t, %1; cvt.u32.u64 %0, t; }"
        : "=r"(sb) : "l"(smem));

    const int tid  = threadIdx.x;
    const int lane = tid & 31;
    const int warp = tid >> 5;           // 0..3
    const int wm = warp >> 1, wn = warp & 1;
    const int g = lane >> 2, t = lane & 3;
    const int m0 = blockIdx.y * 128;
    const int n0 = blockIdx.x * 128;
    const int nk = K >> 5;

    const __half* Abase = A + (size_t)m0 * K;
    const __half* Bbase = Bt + (size_t)n0 * K;

    auto load_chunk = [&](int c, int s) {
        const uint32_t base = sb + s * GSTAGE;
        const __half* Ac = Abase + (size_t)c * 32;
        const __half* Bc = Bbase + (size_t)c * 32;
        #pragma unroll
        for (int i = 0; i < 8; i++) {
            const int id  = tid + 128 * i;        // 0..1023
            const int ab  = id >> 9;              // 0 = A, 1 = B
            const int r   = (id >> 2) & 127;
            const int c16 = id & 3;
            const uint32_t off = ab * 10240u + (uint32_t)r * 80 + c16 * 16;
            const __half* src = (ab ? Bc : Ac) + (size_t)r * K + c16 * 8;
            cpa16(base + off, src);
        }
        CP_COMMIT();
    };

    uint32_t aAddr[4], bAddr[4];
    #pragma unroll
    for (int mt = 0; mt < 4; mt++)
        aAddr[mt] = sb + (wm * 64 + mt * 16 + (lane & 15)) * 80
                       + ((lane >> 4) * 8) * 2;
    #pragma unroll
    for (int ntp = 0; ntp < 4; ntp++)
        bAddr[ntp] = sb + 10240
                   + (wn * 64 + ntp * 16 + ((lane >> 4) & 1) * 8 + (lane & 7)) * 80
                   + (((lane >> 3) & 1) * 8) * 2;

    load_chunk(0, 0); load_chunk(1, 1); load_chunk(2, 2);

    float acc[4][8][4];
    #pragma unroll
    for (int mt = 0; mt < 4; mt++)
        #pragma unroll
        for (int nt = 0; nt < 8; nt++)
            #pragma unroll
            for (int j = 0; j < 4; j++) acc[mt][nt][j] = 0.f;

    for (int kt = 0; kt < nk; kt++) {
        const int s = kt & 3;
        if (kt < nk - 2)       CP_WAIT2();
        else if (kt == nk - 2) CP_WAIT1();
        else                   CP_WAIT0();
        __syncthreads();
        if (kt + 3 < nk) load_chunk(kt + 3, (kt + 3) & 3);

        const uint32_t so = (uint32_t)s * GSTAGE;
        #pragma unroll
        for (int kk = 0; kk < 2; kk++) {
            const uint32_t ko = kk * 32;
            uint32_t af[4][4], bf[4][4];
            #pragma unroll
            for (int mt = 0; mt < 4; mt++)
                ldm_x4(af[mt], aAddr[mt] + so + ko);
            #pragma unroll
            for (int ntp = 0; ntp < 4; ntp++)
                ldm_x4(bf[ntp], bAddr[ntp] + so + ko);
            #pragma unroll
            for (int mt = 0; mt < 4; mt++)
                #pragma unroll
                for (int nt = 0; nt < 8; nt++)
                    mma_f16(acc[mt][nt], af[mt], &bf[nt >> 1][(nt & 1) * 2]);
        }
    }

    #pragma unroll
    for (int mt = 0; mt < 4; mt++) {
        const int r0 = m0 + wm * 64 + mt * 16 + g;
        #pragma unroll
        for (int nt = 0; nt < 8; nt++) {
            const int c0 = n0 + wn * 64 + nt * 8 + 2 * t;
            if (sizeof(TC) == 2) {
                *reinterpret_cast<__half2*>((__half*)Cm + (size_t)r0 * N + c0) =
                    __floats2half2_rn(acc[mt][nt][0], acc[mt][nt][1]);
                *reinterpret_cast<__half2*>((__half*)Cm + (size_t)(r0 + 8) * N + c0) =
                    __floats2half2_rn(acc[mt][nt][2], acc[mt][nt][3]);
            } else {
                *reinterpret_cast<float2*>((float*)Cm + (size_t)r0 * N + c0) =
                    make_float2(acc[mt][nt][0], acc[mt][nt][1]);
                *reinterpret_cast<float2*>((float*)Cm + (size_t)(r0 + 8) * N + c0) =
                    make_float2(acc[mt][nt][2], acc[mt][nt][3]);
            }
        }
    }
}

// ---------------------------------------------------------------------------
// attn_f16: BQ=64, BKV=64, 4 warps, online softmax (log2 domain).
// Round-10 critical-path cuts:
//  - per-thread l partials (quad-reduce ONCE after the loop, not per tile)
//  - skip corr-exp2 + oacc rescale when running max did not increase
//  - magic-constant exp2 (no FRND/F2I)
// ---------------------------------------------------------------------------
#define KVSTR   72                      // halves per KV row (144B, odd x 16B)
#define KVROWS  64
#define KVTILE  (KVROWS * KVSTR)        // halves per K (or V) tile
#define KVSTAGE_B (2 * KVTILE * 2)      // bytes per stage (K + V) = 18432
#define ATTN_SMEM (3 * KVSTAGE_B)       // 55296

__global__ __launch_bounds__(128) void attn_f16(
    const __half* __restrict__ qkv, const float* __restrict__ sink,
    __half* __restrict__ y)
{
    extern __shared__ __align__(16) __half KV[];

    const int tid  = threadIdx.x;
    const int lane = tid & 31;
    const int warp = tid >> 5;
    const int g = lane >> 2, t = lane & 3;
    const int qt = (int)gridDim.x - 1 - (int)blockIdx.x;   // longest first
    const int bh = blockIdx.y;
    const int b = bh >> 4, h = bh & 15;
    const int q0 = qt * 64;
    const size_t rowbase = (size_t)b * T_;

    const int rg0 = q0 + warp * 16 + g;
    const int rg1 = rg0 + 8;

    // Q fragments, scale = (1/8)*log2(e) folded in (log2-domain scores)
    uint32_t qa[4][4];
    {
        const __half2 sc = __floats2half2_rn(0.18033688f, 0.18033688f);
        const __half2* qp0 = reinterpret_cast<const __half2*>(
            &qkv[(rowbase + rg0) * QKVN + h * D_]);
        const __half2* qp8 = qp0 + (size_t)8 * QKVN / 2;
        #pragma unroll
        for (int ks = 0; ks < 4; ks++) {
            __half2 v0 = __hmul2(qp0[8 * ks + t], sc);
            __half2 v1 = __hmul2(qp8[8 * ks + t], sc);
            __half2 v2 = __hmul2(qp0[8 * ks + t + 4], sc);
            __half2 v3 = __hmul2(qp8[8 * ks + t + 4], sc);
            qa[ks][0] = *reinterpret_cast<uint32_t*>(&v0);
            qa[ks][1] = *reinterpret_cast<uint32_t*>(&v1);
            qa[ks][2] = *reinterpret_cast<uint32_t*>(&v2);
            qa[ks][3] = *reinterpret_cast<uint32_t*>(&v3);
        }
    }

    // ldmatrix base addresses (stage 0)
    uint32_t sbase;
    asm("{ .reg .u64 tt; cvta.to.shared.u64 tt, %1; cvt.u32.u64 %0, tt; }"
        : "=r"(sbase) : "l"(KV));
    uint32_t addrK[4], addrV[4];
    {
        const int kvK = ((lane >> 4) & 1) * 8 + (lane & 7);
        const int dK  = ((lane >> 3) & 1) * 8;
        #pragma unroll
        for (int kg = 0; kg < 4; kg++)
            addrK[kg] = sbase + ((kvK + 16 * kg) * KVSTR + dK) * 2;
        const uint32_t vbase = sbase + KVTILE * 2;
        const int kvV = ((lane >> 3) & 1) * 8 + (lane & 7);
        #pragma unroll
        for (int dtp = 0; dtp < 4; dtp++) {
            const int dV = dtp * 16 + ((lane >> 4) & 1) * 8;
            addrV[dtp] = vbase + (kvV * KVSTR + dV) * 2;
        }
    }

    // KV tile loader: 64 rows x (K+V) = 16KB per stage, 8 x 16B per thread
    auto load_kv = [&](int j, int s) {
        const uint32_t base = sbase + (uint32_t)s * KVSTAGE_B;
        const int j0 = j * 64;
        #pragma unroll
        for (int i = 0; i < 8; i++) {
            const int id = tid + 128 * i;          // 0..1023
            const int kv = id >> 9;                // 0 = K, 1 = V
            const int r  = (id >> 3) & 63;
            const int c16 = id & 7;
            const size_t src = (rowbase + j0 + r) * QKVN
                             + (size_t)(1 + kv) * H_ * D_ + h * D_ + c16 * 8;
            cpa16(base + kv * (KVTILE * 2) + r * (KVSTR * 2) + c16 * 16,
                  &qkv[src]);
        }
        CP_COMMIT();
    };

    // online softmax state (log2 domain; sink: m = sink*log2e)
    float m0v = sink[h] * 1.44269504f, m1v = m0v;
    float lp0 = 0.25f, lp1 = 0.25f;     // per-thread partials; quad-sum of
                                        // 0.25 gives the sink's l contribution 1
    float oacc[8][4];
    #pragma unroll
    for (int dt = 0; dt < 8; dt++)
        #pragma unroll
        for (int j = 0; j < 4; j++) oacc[dt][j] = 0.f;

    const int ntile = qt + 1;
    load_kv(0, 0);
    if (ntile > 1) load_kv(1, 1);

    for (int j = 0; j < ntile; j++) {
        const int s = j % 3;
        if (j < ntile - 1) CP_WAIT1(); else CP_WAIT0();
        __syncthreads();
        if (j + 2 < ntile) load_kv(j + 2, (j + 2) % 3);

        const uint32_t so = (uint32_t)s * KVSTAGE_B;

        // S (log2 domain) = (Q*scale*log2e) . K^T   [16 x 64 per warp]
        float sacc[8][4];
        #pragma unroll
        for (int nt = 0; nt < 8; nt++)
            #pragma unroll
            for (int jj = 0; jj < 4; jj++) sacc[nt][jj] = 0.f;
        #pragma unroll
        for (int ks = 0; ks < 4; ks++) {
            #pragma unroll
            for (int kg = 0; kg < 4; kg++) {
                uint32_t bk[4];
                ldm_x4(bk, addrK[kg] + so + ks * 32);
                mma_f16(sacc[2 * kg],     qa[ks], &bk[0]);
                mma_f16(sacc[2 * kg + 1], qa[ks], &bk[2]);
            }
        }

        // causal mask (diagonal tile only)
        const int j0 = j * 64;
        if (j0 >= q0) {
            #pragma unroll
            for (int nt = 0; nt < 8; nt++) {
                const int cg = j0 + nt * 8 + 2 * t;
                if (cg     > rg0) sacc[nt][0] = -1e30f;
                if (cg + 1 > rg0) sacc[nt][1] = -1e30f;
                if (cg     > rg1) sacc[nt][2] = -1e30f;
                if (cg + 1 > rg1) sacc[nt][3] = -1e30f;
            }
        }

        // row maxima (in-thread + quad shfl)
        float rmax0 = -1e30f, rmax1 = -1e30f;
        #pragma unroll
        for (int nt = 0; nt < 8; nt++) {
            rmax0 = fmaxf(rmax0, fmaxf(sacc[nt][0], sacc[nt][1]));
            rmax1 = fmaxf(rmax1, fmaxf(sacc[nt][2], sacc[nt][3]));
        }
        rmax0 = fmaxf(rmax0, __shfl_xor_sync(0xffffffffu, rmax0, 1));
        rmax0 = fmaxf(rmax0, __shfl_xor_sync(0xffffffffu, rmax0, 2));
        rmax1 = fmaxf(rmax1, __shfl_xor_sync(0xffffffffu, rmax1, 1));
        rmax1 = fmaxf(rmax1, __shfl_xor_sync(0xffffffffu, rmax1, 2));

        const float mn0 = fmaxf(m0v, rmax0);
        const float mn1 = fmaxf(m1v, rmax1);

        // rescale only when the running max increased (quad-uniform branch)
        if (mn0 > m0v || mn1 > m1v) {
            const float corr0 = exp2_fast(m0v - mn0);
            const float corr1 = exp2_fast(m1v - mn1);
            lp0 *= corr0; lp1 *= corr1;
            #pragma unroll
            for (int dt = 0; dt < 8; dt++) {
                oacc[dt][0] *= corr0; oacc[dt][1] *= corr0;
                oacc[dt][2] *= corr1; oacc[dt][3] *= corr1;
            }
            m0v = mn0; m1v = mn1;
        }

        // P = 2^(S - m); pack to mma A-fragments; per-thread partial sums
        uint32_t pa[4][4];
        #pragma unroll
        for (int kg = 0; kg < 4; kg++) {
            #pragma unroll
            for (int nn = 0; nn < 2; nn++) {
                const int nt = kg * 2 + nn;
                const float p0 = exp2_fast(sacc[nt][0] - m0v);
                const float p1 = exp2_fast(sacc[nt][1] - m0v);
                const float p2 = exp2_fast(sacc[nt][2] - m1v);
                const float p3 = exp2_fast(sacc[nt][3] - m1v);
                lp0 += p0 + p1;
                lp1 += p2 + p3;
                pa[kg][nn * 2 + 0] = pack2(p0, p1);
                pa[kg][nn * 2 + 1] = pack2(p2, p3);
            }
        }

        // O += P . V
        #pragma unroll
        for (int kg = 0; kg < 4; kg++) {
            const uint32_t koff = so + kg * (16 * KVSTR * 2);
            uint32_t bv[4][4];
            #pragma unroll
            for (int dtp = 0; dtp < 4; dtp++)
                ldm_x4t(bv[dtp], addrV[dtp] + koff);
            #pragma unroll
            for (int dt = 0; dt < 8; dt++)
                mma_f16(oacc[dt], pa[kg], &bv[dt >> 1][(dt & 1) * 2]);
        }
    }

    // final l reduction (once).  lp includes the per-thread 0.25 sink share,
    // but that was scaled by all corr factors since t=0; the sink term must
    // be exp2(sink*log2e - m_final).  Correct by removing the scaled share
    // and adding the exact one.
    // lp started at 0.25 with m = sink*log2e; product of all corr factors
    // equals exp2(sink*log2e - m_final), so the accumulated sink share is
    // already 0.25 * exp2(sink*log2e - m_final) — exact.  No correction.
    float l0 = lp0, l1 = lp1;
    l0 += __shfl_xor_sync(0xffffffffu, l0, 1);
    l0 += __shfl_xor_sync(0xffffffffu, l0, 2);
    l1 += __shfl_xor_sync(0xffffffffu, l1, 1);
    l1 += __shfl_xor_sync(0xffffffffu, l1, 2);
    const float inv0 = 1.f / l0, inv1 = 1.f / l1;

    __half2* yp0 = reinterpret_cast<__half2*>(&y[(rowbase + rg0) * C_ + h * D_]);
    __half2* yp1 = reinterpret_cast<__half2*>(&y[(rowbase + rg1) * C_ + h * D_]);
    #pragma unroll
    for (int dt = 0; dt < 8; dt++) {
        yp0[4 * dt + t] = __floats2half2_rn(oacc[dt][0] * inv0, oacc[dt][1] * inv0);
        yp1[4 * dt + t] = __floats2half2_rn(oacc[dt][2] * inv1, oacc[dt][3] * inv1);
    }
}

// ---------------------------------------------------------------------------
extern "C" void kernel_launch(void* const* d_in, const int* in_sizes, int n_in,
                              void* d_out, int out_size)
{
    const float* x      = (const float*)d_in[0];   // [2,2048,1024]
    const float* w_qkv  = (const float*)d_in[1];   // [1024,3072]
    const float* w_proj = (const float*)d_in[2];   // [1024,1024]
    const float* sink   = (const float*)d_in[3];   // [16]
    float* out = (float*)d_out;                    // [4096,1024]

    __half *xh, *wqT, *wpT, *qkv, *yb;
    cudaGetSymbolAddress((void**)&xh,  g_xh);
    cudaGetSymbolAddress((void**)&wqT, g_wqT);
    cudaGetSymbolAddress((void**)&wpT, g_wpT);
    cudaGetSymbolAddress((void**)&qkv, g_qkv);
    cudaGetSymbolAddress((void**)&yb,  g_y);

    cudaFuncSetAttribute(gemm_cp<__half>,
        cudaFuncAttributeMaxDynamicSharedMemorySize, GEMM_SMEM);
    cudaFuncSetAttribute(gemm_cp<float>,
        cudaFuncAttributeMaxDynamicSharedMemorySize, GEMM_SMEM);
    cudaFuncSetAttribute(attn_f16,
        cudaFuncAttributeMaxDynamicSharedMemorySize, ATTN_SMEM);

    convert_x<<<(M_ * C_ / 4 + 255) / 256, 256>>>(x, xh, M_ * C_ / 4);
    transpose_w<<<dim3(QKVN / 32, C_ / 32), dim3(32, 8)>>>(w_qkv, wqT, C_, QKVN);
    transpose_w<<<dim3(C_ / 32, C_ / 32), dim3(32, 8)>>>(w_proj, wpT, C_, C_);

    gemm_cp<__half><<<dim3(QKVN / 128, M_ / 128), 128, GEMM_SMEM>>>(
        xh, wqT, qkv, M_, QKVN, C_);
    attn_f16<<<dim3(T_ / 64, B_ * H_), 128, ATTN_SMEM>>>(qkv, sink, yb);
    gemm_cp<float><<<dim3(C_ / 128, M_ / 128), 128, GEMM_SMEM>>>(
        yb, wpT, out, M_, C_, C_);
}